// round 7
// baseline (speedup 1.0000x reference)
#include <cuda_runtime.h>
#include <cuda_bf16.h>
#include <stdint.h>
#include <math.h>

typedef unsigned int u32;

// Problem constants
constexpr int B_   = 2;
constexpr int S_   = 2048;
constexpr int HID_ = 1024;
constexpr int NH_  = 16;
constexpr int DK_  = 64;
constexpr int M_   = B_ * S_;   // 4096
constexpr int K_   = 1024;
constexpr int N_   = 1024;

// ---------------------------------------------------------------------------
// Scratch (device globals; no allocation allowed)
// ---------------------------------------------------------------------------
__device__ float g_q  [B_ * NH_ * S_ * DK_];
__device__ float g_k  [B_ * NH_ * S_ * DK_];
__device__ float g_v  [B_ * NH_ * S_ * DK_];
__device__ float g_att[B_ * S_ * HID_];
__device__ float g_p  [B_ * NH_ * S_ * S_];     // raw masked scores, 1 GiB

// bf16 hi/lo split operands for tensor-core GEMMs
__device__ __nv_bfloat16 g_aq_h[M_ * K_];
__device__ __nv_bfloat16 g_aq_l[M_ * K_];
__device__ __nv_bfloat16 g_ak_h[M_ * K_];
__device__ __nv_bfloat16 g_ak_l[M_ * K_];
__device__ __nv_bfloat16 g_av_h[M_ * K_];
__device__ __nv_bfloat16 g_av_l[M_ * K_];
__device__ __nv_bfloat16 g_ao_h[M_ * K_];
__device__ __nv_bfloat16 g_ao_l[M_ * K_];
__device__ __nv_bfloat16 g_wh[4 * N_ * K_];
__device__ __nv_bfloat16 g_wl[4 * N_ * K_];

// ---------------------------------------------------------------------------
// splitting helpers
// ---------------------------------------------------------------------------
__device__ __forceinline__ void split1(float x, __nv_bfloat16* hi, __nv_bfloat16* lo) {
    __nv_bfloat16 h = __float2bfloat16(x);
    *hi = h;
    *lo = __float2bfloat16(x - __bfloat162float(h));
}

__global__ void split_acts_kernel(const float* __restrict__ q,
                                  const float* __restrict__ k,
                                  const float* __restrict__ v,
                                  const float* __restrict__ bias) {
    int i = blockIdx.x * blockDim.x + threadIdx.x;
    if (i < M_ * K_) {
        float f = 1.0f + bias[i >> 10];
        split1(q[i],     &g_aq_h[i], &g_aq_l[i]);
        split1(k[i] * f, &g_ak_h[i], &g_ak_l[i]);
        split1(v[i] * f, &g_av_h[i], &g_av_l[i]);
    }
}

__global__ void split_w_kernel(const float* __restrict__ w,
                               __nv_bfloat16* __restrict__ hi,
                               __nv_bfloat16* __restrict__ lo) {
    int i = blockIdx.x * blockDim.x + threadIdx.x;
    if (i < N_ * K_) split1(w[i], &hi[i], &lo[i]);
}

__global__ void split_att_kernel() {
    int i = blockIdx.x * blockDim.x + threadIdx.x;
    if (i < M_ * K_) split1(g_att[i], &g_ao_h[i], &g_ao_l[i]);
}

// ---------------------------------------------------------------------------
// warp-MMA primitives
// ---------------------------------------------------------------------------
__device__ __forceinline__ void ldsm4(u32 addr, u32& r0, u32& r1, u32& r2, u32& r3) {
    asm volatile("ldmatrix.sync.aligned.m8n8.x4.shared.b16 {%0,%1,%2,%3}, [%4];"
                 : "=r"(r0), "=r"(r1), "=r"(r2), "=r"(r3) : "r"(addr));
}

__device__ __forceinline__ void mma16816(float* c, const u32* a, u32 b0, u32 b1) {
    asm volatile("mma.sync.aligned.m16n8k16.row.col.f32.bf16.bf16.f32 "
                 "{%0,%1,%2,%3}, {%4,%5,%6,%7}, {%8,%9}, {%0,%1,%2,%3};"
                 : "+f"(c[0]), "+f"(c[1]), "+f"(c[2]), "+f"(c[3])
                 : "r"(a[0]), "r"(a[1]), "r"(a[2]), "r"(a[3]), "r"(b0), "r"(b1));
}

// ---------------------------------------------------------------------------
// Tensor-core GEMM: C = A @ W^T + bias, A [M,K], W [N,K], bf16 hi/lo split.
// Block 128x128, k-tile 64, 256 threads = 8 warps, each warp 32(m) x 64(n).
// MODE 0: C row-major [M,1024];  MODE 1: C in [B,NH,S,DK] layout
// ---------------------------------------------------------------------------
constexpr int LDSB = 72;                           // smem row stride (bf16 elems)
constexpr int SM_TILE = 128 * LDSB;                // bf16 elems per matrix
constexpr int MMA_SMEM = 4 * SM_TILE * 2;          // bytes = 73728

template <int MODE>
__global__ __launch_bounds__(256)
void mma_gemm(const __nv_bfloat16* __restrict__ Ahp, const __nv_bfloat16* __restrict__ Alp,
              const __nv_bfloat16* __restrict__ Whp, const __nv_bfloat16* __restrict__ Wlp,
              const float* __restrict__ bias, float* __restrict__ C) {
    extern __shared__ __nv_bfloat16 sm[];
    const u32 smu = (u32)__cvta_generic_to_shared(sm);
    const u32 OFF_AL = (u32)SM_TILE * 2u;
    const u32 OFF_BH = 2u * (u32)SM_TILE * 2u;
    const u32 OFF_BL = 3u * (u32)SM_TILE * 2u;

    const int tid    = threadIdx.x;
    const int lane   = tid & 31;
    const int warpid = tid >> 5;
    const int warp_m = (warpid & 3) * 32;
    const int warp_n = (warpid >> 2) * 64;
    const int m0 = blockIdx.y * 128;
    const int n0 = blockIdx.x * 128;

    float acc[2][8][4];
#pragma unroll
    for (int i = 0; i < 2; i++) {
#pragma unroll
        for (int j = 0; j < 8; j++) {
#pragma unroll
            for (int t = 0; t < 4; t++) acc[i][j][t] = 0.0f;
        }
    }

    const int a_row  = lane & 15;
    const int a_seg  = (lane >> 4) * 8;
    const int b_nrow = (lane & 7) + ((lane >> 4) & 1) * 8;
    const int b_koff = ((lane >> 3) & 1) * 8;

    for (int k0 = 0; k0 < K_; k0 += 64) {
        __syncthreads();
#pragma unroll
        for (int i = 0; i < 4; i++) {
            int idx = tid + i * 256;            // 0..1023
            int r = idx >> 3;                   // 0..127
            int q = idx & 7;                    // 0..7
            int so = r * LDSB + q * 8;
            size_t ga = (size_t)(m0 + r) * K_ + k0 + q * 8;
            size_t gw = (size_t)(n0 + r) * K_ + k0 + q * 8;
            *(uint4*)&sm[so]               = *(const uint4*)&Ahp[ga];
            *(uint4*)&sm[SM_TILE + so]     = *(const uint4*)&Alp[ga];
            *(uint4*)&sm[2 * SM_TILE + so] = *(const uint4*)&Whp[gw];
            *(uint4*)&sm[3 * SM_TILE + so] = *(const uint4*)&Wlp[gw];
        }
        __syncthreads();

#pragma unroll
        for (int ks = 0; ks < 4; ks++) {
            u32 ra_h[2][4];
            u32 ra_l[2][4];
            u32 rb_h[8][2];
            u32 rb_l[8][2];
#pragma unroll
            for (int mf = 0; mf < 2; mf++) {
                u32 aoff = 2u * (u32)((warp_m + mf * 16 + a_row) * LDSB + ks * 16 + a_seg);
                ldsm4(smu + aoff, ra_h[mf][0], ra_h[mf][1], ra_h[mf][2], ra_h[mf][3]);
                ldsm4(smu + OFF_AL + aoff, ra_l[mf][0], ra_l[mf][1], ra_l[mf][2], ra_l[mf][3]);
            }
#pragma unroll
            for (int np = 0; np < 4; np++) {
                u32 boff = 2u * (u32)((warp_n + np * 16 + b_nrow) * LDSB + ks * 16 + b_koff);
                ldsm4(smu + OFF_BH + boff, rb_h[2 * np][0], rb_h[2 * np][1], rb_h[2 * np + 1][0], rb_h[2 * np + 1][1]);
                ldsm4(smu + OFF_BL + boff, rb_l[2 * np][0], rb_l[2 * np][1], rb_l[2 * np + 1][0], rb_l[2 * np + 1][1]);
            }
#pragma unroll
            for (int mf = 0; mf < 2; mf++) {
#pragma unroll
                for (int nf = 0; nf < 8; nf++) {
                    mma16816(acc[mf][nf], ra_h[mf], rb_h[nf][0], rb_h[nf][1]);
                    mma16816(acc[mf][nf], ra_h[mf], rb_l[nf][0], rb_l[nf][1]);
                    mma16816(acc[mf][nf], ra_l[mf], rb_h[nf][0], rb_h[nf][1]);
                }
            }
        }
    }

    // epilogue
#pragma unroll
    for (int mf = 0; mf < 2; mf++) {
        const int r0 = m0 + warp_m + mf * 16 + (lane >> 2);
#pragma unroll
        for (int nf = 0; nf < 8; nf++) {
            const int c = n0 + warp_n + nf * 8 + (lane & 3) * 2;
            const float bc0 = bias[c];
            const float bc1 = bias[c + 1];
            float v00 = acc[mf][nf][0] + bc0;
            float v01 = acc[mf][nf][1] + bc1;
            float v10 = acc[mf][nf][2] + bc0;
            float v11 = acc[mf][nf][3] + bc1;
            if (MODE == 0) {
                C[(size_t)r0 * N_ + c]           = v00;
                C[(size_t)r0 * N_ + c + 1]       = v01;
                C[(size_t)(r0 + 8) * N_ + c]     = v10;
                C[(size_t)(r0 + 8) * N_ + c + 1] = v11;
            } else {
                const int h = c >> 6;
                const int d = c & 63;
                int m1 = r0;
                int bb = m1 >> 11;
                int ss = m1 & (S_ - 1);
                size_t base0 = ((size_t)(bb * NH_ + h) * S_ + ss) * DK_ + d;
                C[base0]     = v00;
                C[base0 + 1] = v01;
                int m2 = r0 + 8;
                bb = m2 >> 11;
                ss = m2 & (S_ - 1);
                size_t base1 = ((size_t)(bb * NH_ + h) * S_ + ss) * DK_ + d;
                C[base1]     = v10;
                C[base1 + 1] = v11;
            }
        }
    }
}

// ---------------------------------------------------------------------------
// 3a) QK^T: per (b,h), 128x128 score tile, GEMM-style (unchanged from R3)
// ---------------------------------------------------------------------------
__global__ __launch_bounds__(256)
void qk_kernel(const float* __restrict__ Q, const float* __restrict__ K,
               const int* __restrict__ mask, float* __restrict__ P) {
    extern __shared__ float smf[];
    float* Qs = smf;                    // [64][128]
    float* Ks = smf + DK_ * 128;        // [64][128]
    int*   msk = (int*)(smf + 2 * DK_ * 128);

    const int tid = threadIdx.x;
    const int bh  = blockIdx.z;
    const int b   = bh >> 4;
    const int q0  = blockIdx.y * 128;
    const int k0  = blockIdx.x * 128;

    const float* Qb = Q + (size_t)bh * S_ * DK_;
    const float* Kb = K + (size_t)bh * S_ * DK_;
    float*       Pb = P + (size_t)bh * S_ * S_;

#pragma unroll
    for (int i = 0; i < 8; i++) {
        int f = tid + i * 256;
        int r = f >> 4;
        int c = (f & 15) * 4;
        float4 qv = *(const float4*)(Qb + (size_t)(q0 + r) * DK_ + c);
        Qs[(c + 0) * 128 + r] = qv.x; Qs[(c + 1) * 128 + r] = qv.y;
        Qs[(c + 2) * 128 + r] = qv.z; Qs[(c + 3) * 128 + r] = qv.w;
        float4 kv = *(const float4*)(Kb + (size_t)(k0 + r) * DK_ + c);
        Ks[(c + 0) * 128 + r] = kv.x; Ks[(c + 1) * 128 + r] = kv.y;
        Ks[(c + 2) * 128 + r] = kv.z; Ks[(c + 3) * 128 + r] = kv.w;
    }
    if (tid < 128) msk[tid] = mask[b * S_ + k0 + tid];
    __syncthreads();

    const int tx = tid & 15;
    const int ty = tid >> 4;

    float acc[8][8];
#pragma unroll
    for (int i = 0; i < 8; i++) {
#pragma unroll
        for (int j = 0; j < 8; j++) acc[i][j] = 0.0f;
    }

#pragma unroll 4
    for (int d = 0; d < DK_; d++) {
        float4 a0 = *(const float4*)&Qs[d * 128 + ty * 8];
        float4 a1 = *(const float4*)&Qs[d * 128 + ty * 8 + 4];
        float4 b0 = *(const float4*)&Ks[d * 128 + tx * 8];
        float4 b1 = *(const float4*)&Ks[d * 128 + tx * 8 + 4];
        float af[8] = {a0.x, a0.y, a0.z, a0.w, a1.x, a1.y, a1.z, a1.w};
        float bf[8] = {b0.x, b0.y, b0.z, b0.w, b1.x, b1.y, b1.z, b1.w};
#pragma unroll
        for (int i = 0; i < 8; i++) {
#pragma unroll
            for (int j = 0; j < 8; j++) acc[i][j] += af[i] * bf[j];
        }
    }

    int mj[8];
#pragma unroll
    for (int j = 0; j < 8; j++) mj[j] = msk[tx * 8 + j];
#pragma unroll
    for (int i = 0; i < 8; i++) {
        float* prow = Pb + (size_t)(q0 + ty * 8 + i) * S_ + k0 + tx * 8;
#pragma unroll
        for (int j = 0; j < 8; j++)
            prow[j] = mj[j] ? acc[i][j] * 0.125f : -10000.0f;
    }
}

// ---------------------------------------------------------------------------
// 3b) fused softmax + P@V (unchanged from R3)
// ---------------------------------------------------------------------------
__global__ __launch_bounds__(256)
void pv_kernel(const float* __restrict__ P, const float* __restrict__ V,
               float* __restrict__ out) {
    __shared__ float As[16][129];
    __shared__ float Bs[16][64];
    __shared__ float mxs[128];
    __shared__ float rinv[128];

    const int tid = threadIdx.x;
    const int bh  = blockIdx.y;
    const int b   = bh >> 4;
    const int h   = bh & 15;
    const int q0  = blockIdx.x * 128;

    const float* Pb = P + (size_t)bh * S_ * S_;
    const float* Vb = V + (size_t)bh * S_ * DK_;

    {
        const int lane = tid & 31;
        const int w    = tid >> 5;
        for (int rr = 0; rr < 16; rr++) {
            const int row = w * 16 + rr;
            const float* pr = Pb + (size_t)(q0 + row) * S_;
            float mx = -3.4e38f;
            for (int j = lane; j < S_ / 4; j += 32) {
                float4 x = *(const float4*)(pr + j * 4);
                mx = fmaxf(mx, fmaxf(fmaxf(x.x, x.y), fmaxf(x.z, x.w)));
            }
#pragma unroll
            for (int o = 16; o > 0; o >>= 1)
                mx = fmaxf(mx, __shfl_xor_sync(0xFFFFFFFFu, mx, o));
            float sum = 0.0f;
            for (int j = lane; j < S_ / 4; j += 32) {
                float4 x = *(const float4*)(pr + j * 4);
                sum += __expf(x.x - mx) + __expf(x.y - mx)
                     + __expf(x.z - mx) + __expf(x.w - mx);
            }
#pragma unroll
            for (int o = 16; o > 0; o >>= 1)
                sum += __shfl_xor_sync(0xFFFFFFFFu, sum, o);
            if (lane == 0) { mxs[row] = mx; rinv[row] = 1.0f / sum; }
        }
    }
    __syncthreads();

    const int tx = tid & 15;
    const int ty = tid >> 4;
    float acc[8][4];
#pragma unroll
    for (int i = 0; i < 8; i++) {
#pragma unroll
        for (int j = 0; j < 4; j++) acc[i][j] = 0.0f;
    }

    for (int kt = 0; kt < S_; kt += 16) {
        __syncthreads();
#pragma unroll
        for (int i = 0; i < 2; i++) {
            int f = tid + i * 256;
            int r  = f >> 2;
            int c4 = (f & 3) * 4;
            float4 x = *(const float4*)(Pb + (size_t)(q0 + r) * S_ + kt + c4);
            float m = mxs[r];
            As[c4 + 0][r] = __expf(x.x - m);
            As[c4 + 1][r] = __expf(x.y - m);
            As[c4 + 2][r] = __expf(x.z - m);
            As[c4 + 3][r] = __expf(x.w - m);
        }
        {
            int r = tid >> 4;
            int c = (tid & 15) * 4;
            *(float4*)&Bs[r][c] = *(const float4*)(Vb + (size_t)(kt + r) * DK_ + c);
        }
        __syncthreads();

#pragma unroll
        for (int kk = 0; kk < 16; kk++) {
            float4 bv = *(const float4*)&Bs[kk][tx * 4];
            float af[8];
#pragma unroll
            for (int i = 0; i < 8; i++) af[i] = As[kk][ty * 8 + i];
            float bf[4] = {bv.x, bv.y, bv.z, bv.w};
#pragma unroll
            for (int i = 0; i < 8; i++) {
#pragma unroll
                for (int j = 0; j < 4; j++) acc[i][j] += af[i] * bf[j];
            }
        }
    }

#pragma unroll
    for (int i = 0; i < 8; i++) {
        const int lr = ty * 8 + i;
        const float rv = rinv[lr];
        float4 o;
        o.x = acc[i][0] * rv; o.y = acc[i][1] * rv;
        o.z = acc[i][2] * rv; o.w = acc[i][3] * rv;
        *(float4*)(out + ((size_t)b * S_ + q0 + lr) * HID_ + h * DK_ + tx * 4) = o;
    }
}

// ---------------------------------------------------------------------------
// launch
// ---------------------------------------------------------------------------
extern "C" void kernel_launch(void* const* d_in, const int* in_sizes, int n_in,
                              void* d_out, int out_size) {
    const float* query = (const float*)d_in[0];
    const float* key   = (const float*)d_in[1];
    const float* value = (const float*)d_in[2];
    const float* bias  = (const float*)d_in[3];
    const int*   mask  = (const int*)  d_in[4];
    const float* wq    = (const float*)d_in[5];
    const float* bq    = (const float*)d_in[6];
    const float* wk    = (const float*)d_in[7];
    const float* bk    = (const float*)d_in[8];
    const float* wv    = (const float*)d_in[9];
    const float* bv    = (const float*)d_in[10];
    const float* wo    = (const float*)d_in[11];
    const float* bo    = (const float*)d_in[12];
    float* out = (float*)d_out;

    float *p_q, *p_k, *p_v, *p_att, *p_p;
    cudaGetSymbolAddress((void**)&p_q,   g_q);
    cudaGetSymbolAddress((void**)&p_k,   g_k);
    cudaGetSymbolAddress((void**)&p_v,   g_v);
    cudaGetSymbolAddress((void**)&p_att, g_att);
    cudaGetSymbolAddress((void**)&p_p,   g_p);

    __nv_bfloat16 *p_aqh, *p_aql, *p_akh, *p_akl, *p_avh, *p_avl, *p_aoh, *p_aol, *p_wh, *p_wl;
    cudaGetSymbolAddress((void**)&p_aqh, g_aq_h);
    cudaGetSymbolAddress((void**)&p_aql, g_aq_l);
    cudaGetSymbolAddress((void**)&p_akh, g_ak_h);
    cudaGetSymbolAddress((void**)&p_akl, g_ak_l);
    cudaGetSymbolAddress((void**)&p_avh, g_av_h);
    cudaGetSymbolAddress((void**)&p_avl, g_av_l);
    cudaGetSymbolAddress((void**)&p_aoh, g_ao_h);
    cudaGetSymbolAddress((void**)&p_aol, g_ao_l);
    cudaGetSymbolAddress((void**)&p_wh,  g_wh);
    cudaGetSymbolAddress((void**)&p_wl,  g_wl);

    cudaFuncSetAttribute(mma_gemm<0>, cudaFuncAttributeMaxDynamicSharedMemorySize, MMA_SMEM);
    cudaFuncSetAttribute(mma_gemm<1>, cudaFuncAttributeMaxDynamicSharedMemorySize, MMA_SMEM);

    // 1) split inputs into bf16 hi/lo (K/V scaled by 1+bias)
    {
        const int n = M_ * K_;
        split_acts_kernel<<<(n + 255) / 256, 256>>>(query, key, value, bias);
        const int nw = N_ * K_;
        split_w_kernel<<<(nw + 255) / 256, 256>>>(wq, p_wh + 0 * (size_t)nw, p_wl + 0 * (size_t)nw);
        split_w_kernel<<<(nw + 255) / 256, 256>>>(wk, p_wh + 1 * (size_t)nw, p_wl + 1 * (size_t)nw);
        split_w_kernel<<<(nw + 255) / 256, 256>>>(wv, p_wh + 2 * (size_t)nw, p_wl + 2 * (size_t)nw);
        split_w_kernel<<<(nw + 255) / 256, 256>>>(wo, p_wh + 3 * (size_t)nw, p_wl + 3 * (size_t)nw);
    }

    // 2) projections on tensor cores (write [B,NH,S,DK] fp32)
    {
        const size_t nw = (size_t)N_ * K_;
        dim3 grid(N_ / 128, M_ / 128);   // (8, 32)
        mma_gemm<1><<<grid, 256, MMA_SMEM>>>(p_aqh, p_aql, p_wh + 0 * nw, p_wl + 0 * nw, bq, p_q);
        mma_gemm<1><<<grid, 256, MMA_SMEM>>>(p_akh, p_akl, p_wh + 1 * nw, p_wl + 1 * nw, bk, p_k);
        mma_gemm<1><<<grid, 256, MMA_SMEM>>>(p_avh, p_avl, p_wh + 2 * nw, p_wl + 2 * nw, bv, p_v);
    }

    // 3a) QK^T -> raw masked scores
    {
        const int smem = (2 * DK_ * 128) * sizeof(float) + 128 * sizeof(int);
        cudaFuncSetAttribute(qk_kernel,
                             cudaFuncAttributeMaxDynamicSharedMemorySize, smem);
        dim3 grid(S_ / 128, S_ / 128, B_ * NH_);
        qk_kernel<<<grid, 256, smem>>>(p_q, p_k, mask, p_p);
    }

    // 3b) fused softmax + P@V
    {
        dim3 grid(S_ / 128, B_ * NH_);
        pv_kernel<<<grid, 256>>>(p_p, p_v, p_att);
    }

    // 4) output projection on tensor cores
    {
        const int n = M_ * K_;
        split_att_kernel<<<(n + 255) / 256, 256>>>();
        const size_t nw = (size_t)N_ * K_;
        dim3 grid(N_ / 128, M_ / 128);
        mma_gemm<0><<<grid, 256, MMA_SMEM>>>(p_aoh, p_aol, p_wh + 3 * nw, p_wl + 3 * nw, bo, out);
    }
}

// round 10
// speedup vs baseline: 1.3343x; 1.3343x over previous
#include <cuda_runtime.h>
#include <cuda_bf16.h>
#include <stdint.h>
#include <math.h>

// Problem constants
constexpr int B_   = 2;
constexpr int S_   = 2048;
constexpr int HID_ = 1024;
constexpr int NH_  = 16;
constexpr int DK_  = 64;
constexpr int M_   = B_ * S_;   // 4096 rows for projection GEMMs

// ---------------------------------------------------------------------------
// Scratch (device globals; no allocation allowed)
// ---------------------------------------------------------------------------
__device__ float g_kin[B_ * S_ * HID_];   // key  * (1+bias)
__device__ float g_vin[B_ * S_ * HID_];   // value* (1+bias)
__device__ float g_q  [B_ * NH_ * S_ * DK_];
__device__ float g_k  [B_ * NH_ * S_ * DK_];
__device__ float g_v  [B_ * NH_ * S_ * DK_];
__device__ float g_att[B_ * S_ * HID_];   // attention output, [B,S,HID]

// ---------------------------------------------------------------------------
// 1) scale K/V by (1 + bias)
// ---------------------------------------------------------------------------
__global__ void scale_kv_kernel(const float* __restrict__ key,
                                const float* __restrict__ value,
                                const float* __restrict__ bias) {
    int i = blockIdx.x * blockDim.x + threadIdx.x;
    const int n = B_ * S_ * HID_;
    if (i < n) {
        int row = i / HID_;              // b*S + s
        float f = 1.0f + bias[row];
        g_kin[i] = key[i]   * f;
        g_vin[i] = value[i] * f;
    }
}

// ---------------------------------------------------------------------------
// 2) SGEMM: C = A @ W^T + bias (unchanged from the passing R3 kernel)
//    MODE 0: C row-major [M,1024];  MODE 1: C in [B,NH,S,DK] layout
// ---------------------------------------------------------------------------
template <int MODE>
__global__ __launch_bounds__(256)
void sgemm_kernel(const float* __restrict__ A,
                  const float* __restrict__ W,
                  const float* __restrict__ bias,
                  float* __restrict__ C) {
    constexpr int K = 1024;
    constexpr int N = 1024;

    __shared__ float As[8][128];
    __shared__ float Bs[8][128];

    const int tid = threadIdx.x;
    const int tx  = tid % 16;      // n-dim
    const int ty  = tid / 16;      // m-dim
    const int m0  = blockIdx.y * 128;
    const int n0  = blockIdx.x * 128;

    const int lrow = tid >> 1;           // 0..127
    const int lcol = (tid & 1) * 4;      // 0 or 4

    float acc[8][8];
#pragma unroll
    for (int i = 0; i < 8; i++)
#pragma unroll
        for (int j = 0; j < 8; j++) acc[i][j] = 0.0f;

    const float* Aptr = A + (m0 + lrow) * K + lcol;
    const float* Wptr = W + (n0 + lrow) * K + lcol;

    for (int k0 = 0; k0 < K; k0 += 8) {
        float4 a  = *(const float4*)(Aptr + k0);
        float4 bw = *(const float4*)(Wptr + k0);
        __syncthreads();
        As[lcol + 0][lrow] = a.x;  As[lcol + 1][lrow] = a.y;
        As[lcol + 2][lrow] = a.z;  As[lcol + 3][lrow] = a.w;
        Bs[lcol + 0][lrow] = bw.x; Bs[lcol + 1][lrow] = bw.y;
        Bs[lcol + 2][lrow] = bw.z; Bs[lcol + 3][lrow] = bw.w;
        __syncthreads();

#pragma unroll
        for (int kk = 0; kk < 8; kk++) {
            float af[8], bf[8];
#pragma unroll
            for (int i = 0; i < 8; i++) af[i] = As[kk][ty * 8 + i];
#pragma unroll
            for (int j = 0; j < 8; j++) bf[j] = Bs[kk][tx * 8 + j];
#pragma unroll
            for (int i = 0; i < 8; i++)
#pragma unroll
                for (int j = 0; j < 8; j++) acc[i][j] += af[i] * bf[j];
        }
    }

#pragma unroll
    for (int i = 0; i < 8; i++) {
        int m = m0 + ty * 8 + i;
#pragma unroll
        for (int j = 0; j < 8; j++) {
            int n = n0 + tx * 8 + j;
            float val = acc[i][j] + bias[n];
            if (MODE == 0) {
                C[m * N + n] = val;
            } else {
                int b = m >> 11;          // m / S_
                int s = m & (S_ - 1);
                int h = n >> 6;           // n / DK_
                int d = n & (DK_ - 1);
                C[((b * NH_ + h) * S_ + s) * DK_ + d] = val;
            }
        }
    }
}

// ---------------------------------------------------------------------------
// 3) Fused flash attention: per (b,h), 64 q-rows per CTA, online softmax.
//    grid (S/64, NH, B), 256 threads (16x16, 4x4 register tiles).
//    Exact in fp32 (same math as full-row softmax).
//    Dynamic smem layout (floats):
//      Qs [64][64] (d-major)      @ 0
//      Ks [64][64] (d-major)      @ 4096
//      Vs [64][64] (k-major)      @ 8192
//      ST [64][65] (k-major, P^T) @ 12288
//      alpha[64]                  @ 16448
//      linv [64]                  @ 16512
//      msk  [64] (int)            @ 16576
// ---------------------------------------------------------------------------
constexpr int FLASH_SMEM = (16576 + 64) * 4;   // 66560 bytes

__global__ __launch_bounds__(256)
void flash_kernel(const float* __restrict__ Q, const float* __restrict__ K,
                  const float* __restrict__ V, const int* __restrict__ mask,
                  float* __restrict__ out) {
    extern __shared__ float sm[];
    float* Qs    = sm;            // [d][q]
    float* Ks    = sm + 4096;     // [d][k]
    float* Vs    = sm + 8192;     // [k][d]
    float* ST    = sm + 12288;    // [k][q], stride 65
    float* alf   = sm + 16448;    // per-row alpha of current tile
    float* linv  = sm + 16512;    // final 1/l
    int*   msk   = (int*)(sm + 16576);

    const int tid = threadIdx.x;
    const int tx  = tid & 15;
    const int ty  = tid >> 4;
    const int b   = blockIdx.z;
    const int h   = blockIdx.y;
    const int q0  = blockIdx.x * 64;
    const int bh  = b * NH_ + h;

    const float* Qb = Q + (size_t)bh * S_ * DK_;
    const float* Kb = K + (size_t)bh * S_ * DK_;
    const float* Vb = V + (size_t)bh * S_ * DK_;
    const int*   mb = mask + b * S_;

    // load Q tile transposed into Qs[d][q]
#pragma unroll
    for (int i = 0; i < 4; i++) {
        int f = tid + i * 256;          // 0..1023
        int r = f >> 4;                 // q 0..63
        int c = (f & 15) * 4;           // d 0..60
        float4 qv = *(const float4*)(Qb + (size_t)(q0 + r) * DK_ + c);
        Qs[(c + 0) * 64 + r] = qv.x;
        Qs[(c + 1) * 64 + r] = qv.y;
        Qs[(c + 2) * 64 + r] = qv.z;
        Qs[(c + 3) * 64 + r] = qv.w;
    }

    float Ob[4][4];
#pragma unroll
    for (int i = 0; i < 4; i++)
#pragma unroll
        for (int j = 0; j < 4; j++) Ob[i][j] = 0.0f;

    const int r    = ty * 4 + (tx & 3);   // row this thread scans
    const int k0s  = (tx >> 2) * 16;      // k segment for the scan
    float m_row = -1.0e30f;
    float l_row = 0.0f;

    for (int kt = 0; kt < S_; kt += 64) {
        __syncthreads();   // protect Ks/Vs/ST reuse from previous iteration

        // load K tile transposed into Ks[d][k]; V tile direct into Vs[k][d]
#pragma unroll
        for (int i = 0; i < 4; i++) {
            int f = tid + i * 256;
            int rr = f >> 4;            // k 0..63
            int cc = (f & 15) * 4;      // d
            float4 kv = *(const float4*)(Kb + (size_t)(kt + rr) * DK_ + cc);
            Ks[(cc + 0) * 64 + rr] = kv.x;
            Ks[(cc + 1) * 64 + rr] = kv.y;
            Ks[(cc + 2) * 64 + rr] = kv.z;
            Ks[(cc + 3) * 64 + rr] = kv.w;
            float4 vv = *(const float4*)(Vb + (size_t)(kt + rr) * DK_ + cc);
            *(float4*)&Vs[rr * 64 + cc] = vv;
        }
        if (tid < 64) msk[tid] = mb[kt + tid];
        __syncthreads();

        // GEMM1: scores 4x4 per thread (q = ty*4.., k = tx*4..)
        float sacc[4][4];
#pragma unroll
        for (int i = 0; i < 4; i++)
#pragma unroll
            for (int j = 0; j < 4; j++) sacc[i][j] = 0.0f;

#pragma unroll 8
        for (int d = 0; d < DK_; d++) {
            float4 a  = *(const float4*)&Qs[d * 64 + ty * 4];
            float4 bb = *(const float4*)&Ks[d * 64 + tx * 4];
            float af[4] = {a.x, a.y, a.z, a.w};
            float bf[4] = {bb.x, bb.y, bb.z, bb.w};
#pragma unroll
            for (int i = 0; i < 4; i++)
#pragma unroll
                for (int j = 0; j < 4; j++) sacc[i][j] += af[i] * bf[j];
        }

        // mask+scale, store transposed ST[k][q] (stride 65)
#pragma unroll
        for (int j = 0; j < 4; j++) {
            const int mk = msk[tx * 4 + j];
#pragma unroll
            for (int i = 0; i < 4; i++) {
                ST[(tx * 4 + j) * 65 + ty * 4 + i] =
                    mk ? sacc[i][j] * 0.125f : -10000.0f;
            }
        }
        __syncthreads();

        // online softmax row update (4 threads per row, 16 k each)
        float tm = -1.0e30f;
#pragma unroll
        for (int t = 0; t < 16; t++)
            tm = fmaxf(tm, ST[(k0s + t) * 65 + r]);
        tm = fmaxf(tm, __shfl_xor_sync(0xFFFFFFFFu, tm, 4));
        tm = fmaxf(tm, __shfl_xor_sync(0xFFFFFFFFu, tm, 8));

        const float m_new = fmaxf(m_row, tm);
        const float al    = __expf(m_row - m_new);
        float sum = 0.0f;
#pragma unroll
        for (int t = 0; t < 16; t++) {
            float e = __expf(ST[(k0s + t) * 65 + r] - m_new);
            ST[(k0s + t) * 65 + r] = e;
            sum += e;
        }
        sum += __shfl_xor_sync(0xFFFFFFFFu, sum, 4);
        sum += __shfl_xor_sync(0xFFFFFFFFu, sum, 8);
        l_row = l_row * al + sum;
        m_row = m_new;
        if ((tx >> 2) == 0) alf[r] = al;
        __syncthreads();

        // rescale O and accumulate P @ V  (q = ty*4.., d = tx*4..)
        float a0 = alf[ty * 4 + 0];
        float a1 = alf[ty * 4 + 1];
        float a2 = alf[ty * 4 + 2];
        float a3 = alf[ty * 4 + 3];
#pragma unroll
        for (int j = 0; j < 4; j++) {
            Ob[0][j] *= a0; Ob[1][j] *= a1; Ob[2][j] *= a2; Ob[3][j] *= a3;
        }

#pragma unroll 4
        for (int kk = 0; kk < 64; kk++) {
            float p0 = ST[kk * 65 + ty * 4 + 0];
            float p1 = ST[kk * 65 + ty * 4 + 1];
            float p2 = ST[kk * 65 + ty * 4 + 2];
            float p3 = ST[kk * 65 + ty * 4 + 3];
            float4 bv = *(const float4*)&Vs[kk * 64 + tx * 4];
            float bf[4] = {bv.x, bv.y, bv.z, bv.w};
#pragma unroll
            for (int j = 0; j < 4; j++) {
                Ob[0][j] += p0 * bf[j];
                Ob[1][j] += p1 * bf[j];
                Ob[2][j] += p2 * bf[j];
                Ob[3][j] += p3 * bf[j];
            }
        }
    }

    if ((tx >> 2) == 0) linv[r] = 1.0f / l_row;
    __syncthreads();

    // normalize and write to [B,S,HID]
#pragma unroll
    for (int i = 0; i < 4; i++) {
        const float rv = linv[ty * 4 + i];
        float4 o;
        o.x = Ob[i][0] * rv; o.y = Ob[i][1] * rv;
        o.z = Ob[i][2] * rv; o.w = Ob[i][3] * rv;
        *(float4*)(out + ((size_t)b * S_ + q0 + ty * 4 + i) * HID_ + h * DK_ + tx * 4) = o;
    }
}

// ---------------------------------------------------------------------------
// launch
// ---------------------------------------------------------------------------
extern "C" void kernel_launch(void* const* d_in, const int* in_sizes, int n_in,
                              void* d_out, int out_size) {
    const float* query = (const float*)d_in[0];
    const float* key   = (const float*)d_in[1];
    const float* value = (const float*)d_in[2];
    const float* bias  = (const float*)d_in[3];
    const int*   mask  = (const int*)  d_in[4];
    const float* wq    = (const float*)d_in[5];
    const float* bq    = (const float*)d_in[6];
    const float* wk    = (const float*)d_in[7];
    const float* bk    = (const float*)d_in[8];
    const float* wv    = (const float*)d_in[9];
    const float* bv    = (const float*)d_in[10];
    const float* wo    = (const float*)d_in[11];
    const float* bo    = (const float*)d_in[12];
    float* out = (float*)d_out;

    float *p_kin, *p_vin, *p_q, *p_k, *p_v, *p_att;
    cudaGetSymbolAddress((void**)&p_kin, g_kin);
    cudaGetSymbolAddress((void**)&p_vin, g_vin);
    cudaGetSymbolAddress((void**)&p_q,   g_q);
    cudaGetSymbolAddress((void**)&p_k,   g_k);
    cudaGetSymbolAddress((void**)&p_v,   g_v);
    cudaGetSymbolAddress((void**)&p_att, g_att);

    // 1) scale K/V
    {
        const int n = B_ * S_ * HID_;
        scale_kv_kernel<<<(n + 255) / 256, 256>>>(key, value, bias);
    }

    // 2) projections (write [B,NH,S,DK])
    {
        dim3 grid(1024 / 128, M_ / 128);   // (8, 32)
        sgemm_kernel<1><<<grid, 256>>>(query, wq, bq, p_q);
        sgemm_kernel<1><<<grid, 256>>>(p_kin, wk, bk, p_k);
        sgemm_kernel<1><<<grid, 256>>>(p_vin, wv, bv, p_v);
    }

    // 3) fused flash attention
    {
        cudaFuncSetAttribute(flash_kernel,
                             cudaFuncAttributeMaxDynamicSharedMemorySize,
                             FLASH_SMEM);
        dim3 grid(S_ / 64, NH_, B_);       // (32, 16, 2)
        flash_kernel<<<grid, 256, FLASH_SMEM>>>(p_q, p_k, p_v, mask, p_att);
    }

    // 4) output projection (row-major out)
    {
        dim3 grid(1024 / 128, M_ / 128);
        sgemm_kernel<0><<<grid, 256>>>(p_att, wo, bo, out);
    }
}